// round 16
// baseline (speedup 1.0000x reference)
#include <cuda_runtime.h>
#include <cuda_bf16.h>
#include <cstdint>

// Problem constants
#define BATCH   32
#define TSTEPS  500
#define NIN     512
#define NHID    2048
#define MROWS   (TSTEPS * BATCH)   // 16000

// Scratch (device globals; no allocation allowed)
__device__ float          g_cur[(size_t)TSTEPS * BATCH * NHID];   // [t][b][h] fp32, 131 MB
__device__ float          g_WT[(size_t)NHID * NHID];              // WT[h][j] = W_rec[j][h]
__device__ float          g_rowsum[NHID];                         // sum_h W_rec[j][h]
__device__ __nv_bfloat16  g_xb[(size_t)BATCH * TSTEPS * NIN];     // x in bf16
__device__ __nv_bfloat16  g_wb[(size_t)NHID * NIN];               // W_in in bf16

// ---------------------------------------------------------------------------
// Converters
// ---------------------------------------------------------------------------
__global__ void cvt_x_k(const float* __restrict__ in, int n) {
    int i = blockIdx.x * blockDim.x + threadIdx.x;
    if (i < n) g_xb[i] = __float2bfloat16(in[i]);
}
__global__ void cvt_w_k(const float* __restrict__ in, int n) {
    int i = blockIdx.x * blockDim.x + threadIdx.x;
    if (i < n) g_wb[i] = __float2bfloat16(in[i]);
}

// ---------------------------------------------------------------------------
// Transpose W_rec [j][h] -> g_WT [h][j]  (coalesced both ways via smem tile)
// ---------------------------------------------------------------------------
__global__ void transpose_k(const float* __restrict__ W) {
    __shared__ float tile[32][33];
    int h = blockIdx.x * 32 + threadIdx.x;
    int j = blockIdx.y * 32 + threadIdx.y;
    tile[threadIdx.y][threadIdx.x] = W[(size_t)j * NHID + h];
    __syncthreads();
    int h2 = blockIdx.x * 32 + threadIdx.y;
    int j2 = blockIdx.y * 32 + threadIdx.x;
    g_WT[(size_t)h2 * NHID + j2] = tile[threadIdx.x][threadIdx.y];
}

// ---------------------------------------------------------------------------
// Row sums of W_rec: rowsum[j] = sum_h W_rec[j][h]
// ---------------------------------------------------------------------------
__global__ void rowsum_k(const float* __restrict__ W) {
    int j = blockIdx.x;
    float s = 0.f;
    for (int h = threadIdx.x; h < NHID; h += 256)
        s += W[(size_t)j * NHID + h];
    __shared__ float red[256];
    red[threadIdx.x] = s;
    __syncthreads();
    for (int o = 128; o > 0; o >>= 1) {
        if (threadIdx.x < o) red[threadIdx.x] += red[threadIdx.x + o];
        __syncthreads();
    }
    if (threadIdx.x == 0) g_rowsum[j] = red[0];
}

// ---------------------------------------------------------------------------
// Input projection GEMM (bf16 mma.sync, fp32 accum):
//   g_cur[r, c] = sum_k X_row(r)[k] * W_in[c][k] + b_in[c],  r = t*32 + b
//   X_row(r) = x[b, t, :]  (row permutation of x: b = r&31, t = r>>5)
// Tile: BM=128, BN=128, BK=32, 256 threads (8 warps, warp tile 32x64)
// ---------------------------------------------------------------------------
__global__ __launch_bounds__(256) void gemm_k(const float* __restrict__ b_in) {
    constexpr int LD = 40;  // 32 + 8 halves padding (80B row) -> conflict-free-ish
    __shared__ __nv_bfloat16 As[128 * LD];
    __shared__ __nv_bfloat16 Bs[128 * LD];

    const int ntile = blockIdx.x;   // 0..15
    const int mtile = blockIdx.y;   // 0..124
    const int tid  = threadIdx.x;
    const int lane = tid & 31;
    const int warp = tid >> 5;
    const int wm = warp >> 1;       // 0..3  (M)
    const int wn = warp & 1;        // 0..1  (N)

    float acc[2][8][4];
#pragma unroll
    for (int im = 0; im < 2; im++)
#pragma unroll
        for (int in = 0; in < 8; in++)
#pragma unroll
            for (int q = 0; q < 4; q++) acc[im][in][q] = 0.f;

    for (int kt = 0; kt < NIN / 32; ++kt) {
        const int k0 = kt * 32;
#pragma unroll
        for (int i = 0; i < 2; ++i) {
            int v   = tid + i * 256;       // 0..511
            int row = v >> 2;              // 0..127
            int kv  = (v & 3) << 3;        // 0,8,16,24 (halves)
            // A: row permuted from x
            int grow = mtile * 128 + row;
            int bb = grow & 31, tt = grow >> 5;
            uint4 va = *(const uint4*)(g_xb + ((size_t)bb * TSTEPS + tt) * NIN + k0 + kv);
            *(uint4*)(As + row * LD + kv) = va;
            // B: W_in rows (contiguous k)
            int gcol = ntile * 128 + row;
            uint4 vb = *(const uint4*)(g_wb + (size_t)gcol * NIN + k0 + kv);
            *(uint4*)(Bs + row * LD + kv) = vb;
        }
        __syncthreads();

#pragma unroll
        for (int kk = 0; kk < 32; kk += 16) {
            const int kl = kk + ((lane & 3) << 1);
            uint32_t af[2][4];
#pragma unroll
            for (int im = 0; im < 2; im++) {
                int r = wm * 32 + im * 16 + (lane >> 2);
                af[im][0] = *(const uint32_t*)(As + r * LD + kl);
                af[im][1] = *(const uint32_t*)(As + (r + 8) * LD + kl);
                af[im][2] = *(const uint32_t*)(As + r * LD + kl + 8);
                af[im][3] = *(const uint32_t*)(As + (r + 8) * LD + kl + 8);
            }
#pragma unroll
            for (int in = 0; in < 8; in++) {
                int c = wn * 64 + in * 8 + (lane >> 2);
                uint32_t b0 = *(const uint32_t*)(Bs + c * LD + kl);
                uint32_t b1 = *(const uint32_t*)(Bs + c * LD + kl + 8);
#pragma unroll
                for (int im = 0; im < 2; im++) {
                    asm volatile(
                        "mma.sync.aligned.m16n8k16.row.col.f32.bf16.bf16.f32 "
                        "{%0,%1,%2,%3}, {%4,%5,%6,%7}, {%8,%9}, {%0,%1,%2,%3};\n"
                        : "+f"(acc[im][in][0]), "+f"(acc[im][in][1]),
                          "+f"(acc[im][in][2]), "+f"(acc[im][in][3])
                        : "r"(af[im][0]), "r"(af[im][1]), "r"(af[im][2]), "r"(af[im][3]),
                          "r"(b0), "r"(b1));
                }
            }
        }
        __syncthreads();
    }

    // Epilogue: add b_in, store fp32
#pragma unroll
    for (int im = 0; im < 2; im++) {
        int r = mtile * 128 + wm * 32 + im * 16 + (lane >> 2);
#pragma unroll
        for (int in = 0; in < 8; in++) {
            int c = ntile * 128 + wn * 64 + in * 8 + ((lane & 3) << 1);
            float bi0 = b_in[c], bi1 = b_in[c + 1];
            float2 v0 = make_float2(acc[im][in][0] + bi0, acc[im][in][1] + bi1);
            float2 v1 = make_float2(acc[im][in][2] + bi0, acc[im][in][3] + bi1);
            *(float2*)(g_cur + (size_t)r * NHID + c) = v0;
            *(float2*)(g_cur + (size_t)(r + 8) * NHID + c) = v1;
        }
    }
}

// ---------------------------------------------------------------------------
// Scan: one CTA per batch element. 1024 threads, 2 neurons each.
// Recurrent term via adaptive sparse gather of WT rows:
//   mode 0: no spikes -> rec = 0
//   mode 1: all spike -> rec = rowsum (precomputed)
//   mode 2: gather firing set       (n <= 1024)
//   mode 3: rowsum - gather of complement (n > 1024)
// ---------------------------------------------------------------------------
__global__ __launch_bounds__(1024) void scan_k(const float* __restrict__ mem0,
                                               const float* __restrict__ b_rec,
                                               float* __restrict__ out) {
    const int b   = blockIdx.x;
    const int tid = threadIdx.x;
    const int j0  = tid;
    const int j1  = tid + 1024;

    __shared__ unsigned words[64];
    __shared__ int s_mode, s_m, s_cnt;
    __shared__ short list[1024];

    float mem_0 = mem0[(size_t)b * NHID + j0];
    float mem_1 = mem0[(size_t)b * NHID + j1];
    int rf0 = 0, rf1 = 0;
    const float rs0 = g_rowsum[j0], rs1 = g_rowsum[j1];
    const float br0 = b_rec[j0],   br1 = b_rec[j1];

    if (tid == 0) { s_mode = 0; s_m = 0; s_cnt = 0; }
    __syncthreads();

    const float* curb = g_cur + (size_t)b * NHID;  // + t*(BATCH*NHID) + j
    float c0 = curb[j0];
    float c1 = curb[j1];

    for (int t = 0; t < TSTEPS; ++t) {
        // prefetch next step's input current (hide DRAM latency)
        int tn = (t + 1 < TSTEPS) ? (t + 1) : t;
        float n0 = curb[(size_t)tn * (BATCH * NHID) + j0];
        float n1 = curb[(size_t)tn * (BATCH * NHID) + j1];

        // recurrent term from previous step's spikes
        int mode = s_mode;
        int m    = s_m;
        float rec0, rec1;
        if (mode == 0)      { rec0 = 0.f; rec1 = 0.f; }
        else if (mode == 1) { rec0 = rs0; rec1 = rs1; }
        else {
            float a0 = 0.f, a1 = 0.f;
            for (int i = 0; i < m; ++i) {
                int h = list[i];
                const float* wr = g_WT + (size_t)h * NHID;
                a0 += wr[j0];
                a1 += wr[j1];
            }
            if (mode == 2) { rec0 = a0;       rec1 = a1;       }
            else           { rec0 = rs0 - a0; rec1 = rs1 - a1; }
        }

        // LIF update (reset_mechanism='zero', refractory masking)
        rf0 = rf0 > 0 ? rf0 - 1 : 0;
        rf1 = rf1 > 0 ? rf1 - 1 : 0;

        float base0 = 0.95f * (mem_0 + 70.0f) + c0 + rec0 + br0 - 70.0f;
        float base1 = 0.95f * (mem_1 + 70.0f) + c1 + rec1 + br1 - 70.0f;
        mem_0 = (mem_0 > -55.0f) ? 0.0f : base0;   // reset uses OLD mem
        mem_1 = (mem_1 > -55.0f) ? 0.0f : base1;

        bool s0 = (mem_0 > -55.0f) && (rf0 == 0);
        bool s1 = (mem_1 > -55.0f) && (rf1 == 0);
        if (s0) rf0 = 5;
        if (s1) rf1 = 5;

        size_t ob = (size_t)t * (BATCH * NHID) + (size_t)b * NHID;
        out[ob + j0] = s0 ? 1.0f : 0.0f;
        out[ob + j1] = s1 ? 1.0f : 0.0f;

        // build spike bitmask (word k covers neurons [32k, 32k+32))
        unsigned bal0 = __ballot_sync(0xffffffffu, s0);
        unsigned bal1 = __ballot_sync(0xffffffffu, s1);
        int w = tid >> 5;
        if ((tid & 31) == 0) { words[w] = bal0; words[32 + w] = bal1; }
        if (tid == 0) s_cnt = 0;
        __syncthreads();

        // count spikes, choose mode (warp 0)
        if (tid < 32) {
            int v = __popc(words[tid]) + __popc(words[tid + 32]);
            for (int o = 16; o > 0; o >>= 1) v += __shfl_down_sync(0xffffffffu, v, o);
            if (tid == 0) {
                int n = v;
                if (n == 0)         { s_mode = 0; s_m = 0;        }
                else if (n == NHID) { s_mode = 1; s_m = 0;        }
                else if (n <= 1024) { s_mode = 2; s_m = n;        }
                else                { s_mode = 3; s_m = NHID - n; }
            }
        }
        __syncthreads();

        // build index list of the smaller set (only if partially firing)
        int nm = s_mode;
        if (nm >= 2 && tid < 64) {
            unsigned bits = words[tid];
            if (nm == 3) bits = ~bits;
            int cnt  = __popc(bits);
            int base = cnt ? atomicAdd(&s_cnt, cnt) : 0;
            int off  = tid << 5;
            while (bits) {
                int bp = __ffs(bits) - 1;
                list[base++] = (short)(off + bp);
                bits &= bits - 1;
            }
        }
        __syncthreads();

        c0 = n0;
        c1 = n1;
    }
}

// ---------------------------------------------------------------------------
// Launch
// ---------------------------------------------------------------------------
extern "C" void kernel_launch(void* const* d_in, const int* in_sizes, int n_in,
                              void* d_out, int out_size) {
    const float* x     = (const float*)d_in[0];  // [32,500,512]
    const float* mem0  = (const float*)d_in[1];  // [32,2048]
    const float* W_in  = (const float*)d_in[2];  // [2048,512]
    const float* b_in  = (const float*)d_in[3];  // [2048]
    const float* W_rec = (const float*)d_in[4];  // [2048,2048]
    const float* b_rec = (const float*)d_in[5];  // [2048]
    float* out = (float*)d_out;                  // [500,32,2048]

    const int nx = BATCH * TSTEPS * NIN;   // 8,192,000
    const int nw = NHID * NIN;             // 1,048,576

    cvt_x_k<<<(nx + 255) / 256, 256>>>(x, nx);
    cvt_w_k<<<(nw + 255) / 256, 256>>>(W_in, nw);

    dim3 tb(32, 32);
    dim3 tg(NHID / 32, NHID / 32);
    transpose_k<<<tg, tb>>>(W_rec);
    rowsum_k<<<NHID, 256>>>(W_rec);

    dim3 gg(NHID / 128, MROWS / 128);      // (16, 125)
    gemm_k<<<gg, 256>>>(b_in);

    scan_k<<<BATCH, 1024>>>(mem0, b_rec, out);
}

// round 17
// speedup vs baseline: 1.0131x; 1.0131x over previous
#include <cuda_runtime.h>
#include <cuda_bf16.h>
#include <cstdint>

// Problem constants
#define BATCH   32
#define TSTEPS  500
#define NIN     512
#define NHID    2048
#define MROWS   (TSTEPS * BATCH)   // 16000

// Scratch (device globals; no allocation allowed)
__device__ float          g_cur[(size_t)TSTEPS * BATCH * NHID];   // [t][b][h] fp32, 131 MB
__device__ float          g_WT[(size_t)NHID * NHID];              // WT[h][j] = W_rec[j][h]
__device__ float          g_rowsum[NHID];                         // sum_h W_rec[j][h]
__device__ __nv_bfloat16  g_xb[(size_t)BATCH * TSTEPS * NIN];     // x in bf16
__device__ __nv_bfloat16  g_wb[(size_t)NHID * NIN];               // W_in in bf16

// ---------------------------------------------------------------------------
// Converters
// ---------------------------------------------------------------------------
__global__ void cvt_x_k(const float* __restrict__ in, int n) {
    int i = blockIdx.x * blockDim.x + threadIdx.x;
    if (i < n) g_xb[i] = __float2bfloat16(in[i]);
}
__global__ void cvt_w_k(const float* __restrict__ in, int n) {
    int i = blockIdx.x * blockDim.x + threadIdx.x;
    if (i < n) g_wb[i] = __float2bfloat16(in[i]);
}

// ---------------------------------------------------------------------------
// Transpose W_rec [j][h] -> g_WT [h][j]  (coalesced both ways via smem tile)
// ---------------------------------------------------------------------------
__global__ void transpose_k(const float* __restrict__ W) {
    __shared__ float tile[32][33];
    int h = blockIdx.x * 32 + threadIdx.x;
    int j = blockIdx.y * 32 + threadIdx.y;
    tile[threadIdx.y][threadIdx.x] = W[(size_t)j * NHID + h];
    __syncthreads();
    int h2 = blockIdx.x * 32 + threadIdx.y;
    int j2 = blockIdx.y * 32 + threadIdx.x;
    g_WT[(size_t)h2 * NHID + j2] = tile[threadIdx.x][threadIdx.y];
}

// ---------------------------------------------------------------------------
// Row sums of W_rec: rowsum[j] = sum_h W_rec[j][h]
// ---------------------------------------------------------------------------
__global__ void rowsum_k(const float* __restrict__ W) {
    int j = blockIdx.x;
    float s = 0.f;
    for (int h = threadIdx.x; h < NHID; h += 256)
        s += W[(size_t)j * NHID + h];
    __shared__ float red[256];
    red[threadIdx.x] = s;
    __syncthreads();
    for (int o = 128; o > 0; o >>= 1) {
        if (threadIdx.x < o) red[threadIdx.x] += red[threadIdx.x + o];
        __syncthreads();
    }
    if (threadIdx.x == 0) g_rowsum[j] = red[0];
}

// ---------------------------------------------------------------------------
// Input projection GEMM (bf16 mma.sync, fp32 accum):
//   g_cur[r, c] = sum_k X_row(r)[k] * W_in[c][k] + b_in[c],  r = t*32 + b
//   X_row(r) = x[b, t, :]  (row permutation of x: b = r&31, t = r>>5)
// Tile: BM=128, BN=128, BK=32, 256 threads (8 warps, warp tile 32x64)
// ---------------------------------------------------------------------------
__global__ __launch_bounds__(256) void gemm_k(const float* __restrict__ b_in) {
    constexpr int LD = 40;  // 32 + 8 halves padding (80B row) -> conflict-free-ish
    __shared__ __nv_bfloat16 As[128 * LD];
    __shared__ __nv_bfloat16 Bs[128 * LD];

    const int ntile = blockIdx.x;   // 0..15
    const int mtile = blockIdx.y;   // 0..124
    const int tid  = threadIdx.x;
    const int lane = tid & 31;
    const int warp = tid >> 5;
    const int wm = warp >> 1;       // 0..3  (M)
    const int wn = warp & 1;        // 0..1  (N)

    float acc[2][8][4];
#pragma unroll
    for (int im = 0; im < 2; im++)
#pragma unroll
        for (int in = 0; in < 8; in++)
#pragma unroll
            for (int q = 0; q < 4; q++) acc[im][in][q] = 0.f;

    for (int kt = 0; kt < NIN / 32; ++kt) {
        const int k0 = kt * 32;
#pragma unroll
        for (int i = 0; i < 2; ++i) {
            int v   = tid + i * 256;       // 0..511
            int row = v >> 2;              // 0..127
            int kv  = (v & 3) << 3;        // 0,8,16,24 (halves)
            // A: row permuted from x
            int grow = mtile * 128 + row;
            int bb = grow & 31, tt = grow >> 5;
            uint4 va = *(const uint4*)(g_xb + ((size_t)bb * TSTEPS + tt) * NIN + k0 + kv);
            *(uint4*)(As + row * LD + kv) = va;
            // B: W_in rows (contiguous k)
            int gcol = ntile * 128 + row;
            uint4 vb = *(const uint4*)(g_wb + (size_t)gcol * NIN + k0 + kv);
            *(uint4*)(Bs + row * LD + kv) = vb;
        }
        __syncthreads();

#pragma unroll
        for (int kk = 0; kk < 32; kk += 16) {
            const int kl = kk + ((lane & 3) << 1);
            uint32_t af[2][4];
#pragma unroll
            for (int im = 0; im < 2; im++) {
                int r = wm * 32 + im * 16 + (lane >> 2);
                af[im][0] = *(const uint32_t*)(As + r * LD + kl);
                af[im][1] = *(const uint32_t*)(As + (r + 8) * LD + kl);
                af[im][2] = *(const uint32_t*)(As + r * LD + kl + 8);
                af[im][3] = *(const uint32_t*)(As + (r + 8) * LD + kl + 8);
            }
#pragma unroll
            for (int in = 0; in < 8; in++) {
                int c = wn * 64 + in * 8 + (lane >> 2);
                uint32_t b0 = *(const uint32_t*)(Bs + c * LD + kl);
                uint32_t b1 = *(const uint32_t*)(Bs + c * LD + kl + 8);
#pragma unroll
                for (int im = 0; im < 2; im++) {
                    asm volatile(
                        "mma.sync.aligned.m16n8k16.row.col.f32.bf16.bf16.f32 "
                        "{%0,%1,%2,%3}, {%4,%5,%6,%7}, {%8,%9}, {%0,%1,%2,%3};\n"
                        : "+f"(acc[im][in][0]), "+f"(acc[im][in][1]),
                          "+f"(acc[im][in][2]), "+f"(acc[im][in][3])
                        : "r"(af[im][0]), "r"(af[im][1]), "r"(af[im][2]), "r"(af[im][3]),
                          "r"(b0), "r"(b1));
                }
            }
        }
        __syncthreads();
    }

    // Epilogue: add b_in, store fp32
#pragma unroll
    for (int im = 0; im < 2; im++) {
        int r = mtile * 128 + wm * 32 + im * 16 + (lane >> 2);
#pragma unroll
        for (int in = 0; in < 8; in++) {
            int c = ntile * 128 + wn * 64 + in * 8 + ((lane & 3) << 1);
            float bi0 = b_in[c], bi1 = b_in[c + 1];
            float2 v0 = make_float2(acc[im][in][0] + bi0, acc[im][in][1] + bi1);
            float2 v1 = make_float2(acc[im][in][2] + bi0, acc[im][in][3] + bi1);
            *(float2*)(g_cur + (size_t)r * NHID + c) = v0;
            *(float2*)(g_cur + (size_t)(r + 8) * NHID + c) = v1;
        }
    }
}

// ---------------------------------------------------------------------------
// Scan: one CTA per batch element. 1024 threads, 2 neurons each.
// Recurrent term via adaptive sparse gather of WT rows:
//   mode 0: no spikes -> rec = 0
//   mode 1: all spike -> rec = rowsum (precomputed)
//   mode 2: gather firing set       (n <= 1024)
//   mode 3: rowsum - gather of complement (n > 1024)
// ---------------------------------------------------------------------------
__global__ __launch_bounds__(1024) void scan_k(const float* __restrict__ mem0,
                                               const float* __restrict__ b_rec,
                                               float* __restrict__ out) {
    const int b   = blockIdx.x;
    const int tid = threadIdx.x;
    const int j0  = tid;
    const int j1  = tid + 1024;

    __shared__ unsigned words[64];
    __shared__ int s_mode, s_m, s_cnt;
    __shared__ short list[1024];

    float mem_0 = mem0[(size_t)b * NHID + j0];
    float mem_1 = mem0[(size_t)b * NHID + j1];
    int rf0 = 0, rf1 = 0;
    const float rs0 = g_rowsum[j0], rs1 = g_rowsum[j1];
    const float br0 = b_rec[j0],   br1 = b_rec[j1];

    if (tid == 0) { s_mode = 0; s_m = 0; s_cnt = 0; }
    __syncthreads();

    const float* curb = g_cur + (size_t)b * NHID;  // + t*(BATCH*NHID) + j
    float c0 = curb[j0];
    float c1 = curb[j1];

    for (int t = 0; t < TSTEPS; ++t) {
        // prefetch next step's input current (hide DRAM latency)
        int tn = (t + 1 < TSTEPS) ? (t + 1) : t;
        float n0 = curb[(size_t)tn * (BATCH * NHID) + j0];
        float n1 = curb[(size_t)tn * (BATCH * NHID) + j1];

        // recurrent term from previous step's spikes
        int mode = s_mode;
        int m    = s_m;
        float rec0, rec1;
        if (mode == 0)      { rec0 = 0.f; rec1 = 0.f; }
        else if (mode == 1) { rec0 = rs0; rec1 = rs1; }
        else {
            float a0 = 0.f, a1 = 0.f;
            for (int i = 0; i < m; ++i) {
                int h = list[i];
                const float* wr = g_WT + (size_t)h * NHID;
                a0 += wr[j0];
                a1 += wr[j1];
            }
            if (mode == 2) { rec0 = a0;       rec1 = a1;       }
            else           { rec0 = rs0 - a0; rec1 = rs1 - a1; }
        }

        // LIF update (reset_mechanism='zero', refractory masking)
        rf0 = rf0 > 0 ? rf0 - 1 : 0;
        rf1 = rf1 > 0 ? rf1 - 1 : 0;

        float base0 = 0.95f * (mem_0 + 70.0f) + c0 + rec0 + br0 - 70.0f;
        float base1 = 0.95f * (mem_1 + 70.0f) + c1 + rec1 + br1 - 70.0f;
        mem_0 = (mem_0 > -55.0f) ? 0.0f : base0;   // reset uses OLD mem
        mem_1 = (mem_1 > -55.0f) ? 0.0f : base1;

        bool s0 = (mem_0 > -55.0f) && (rf0 == 0);
        bool s1 = (mem_1 > -55.0f) && (rf1 == 0);
        if (s0) rf0 = 5;
        if (s1) rf1 = 5;

        size_t ob = (size_t)t * (BATCH * NHID) + (size_t)b * NHID;
        out[ob + j0] = s0 ? 1.0f : 0.0f;
        out[ob + j1] = s1 ? 1.0f : 0.0f;

        // build spike bitmask (word k covers neurons [32k, 32k+32))
        unsigned bal0 = __ballot_sync(0xffffffffu, s0);
        unsigned bal1 = __ballot_sync(0xffffffffu, s1);
        int w = tid >> 5;
        if ((tid & 31) == 0) { words[w] = bal0; words[32 + w] = bal1; }
        if (tid == 0) s_cnt = 0;
        __syncthreads();

        // count spikes, choose mode (warp 0)
        if (tid < 32) {
            int v = __popc(words[tid]) + __popc(words[tid + 32]);
            for (int o = 16; o > 0; o >>= 1) v += __shfl_down_sync(0xffffffffu, v, o);
            if (tid == 0) {
                int n = v;
                if (n == 0)         { s_mode = 0; s_m = 0;        }
                else if (n == NHID) { s_mode = 1; s_m = 0;        }
                else if (n <= 1024) { s_mode = 2; s_m = n;        }
                else                { s_mode = 3; s_m = NHID - n; }
            }
        }
        __syncthreads();

        // build index list of the smaller set (only if partially firing)
        int nm = s_mode;
        if (nm >= 2 && tid < 64) {
            unsigned bits = words[tid];
            if (nm == 3) bits = ~bits;
            int cnt  = __popc(bits);
            int base = cnt ? atomicAdd(&s_cnt, cnt) : 0;
            int off  = tid << 5;
            while (bits) {
                int bp = __ffs(bits) - 1;
                list[base++] = (short)(off + bp);
                bits &= bits - 1;
            }
        }
        __syncthreads();

        c0 = n0;
        c1 = n1;
    }
}

// ---------------------------------------------------------------------------
// Launch
// ---------------------------------------------------------------------------
extern "C" void kernel_launch(void* const* d_in, const int* in_sizes, int n_in,
                              void* d_out, int out_size) {
    const float* x     = (const float*)d_in[0];  // [32,500,512]
    const float* mem0  = (const float*)d_in[1];  // [32,2048]
    const float* W_in  = (const float*)d_in[2];  // [2048,512]
    const float* b_in  = (const float*)d_in[3];  // [2048]
    const float* W_rec = (const float*)d_in[4];  // [2048,2048]
    const float* b_rec = (const float*)d_in[5];  // [2048]
    float* out = (float*)d_out;                  // [500,32,2048]

    const int nx = BATCH * TSTEPS * NIN;   // 8,192,000
    const int nw = NHID * NIN;             // 1,048,576

    cvt_x_k<<<(nx + 255) / 256, 256>>>(x, nx);
    cvt_w_k<<<(nw + 255) / 256, 256>>>(W_in, nw);

    dim3 tb(32, 32);
    dim3 tg(NHID / 32, NHID / 32);
    transpose_k<<<tg, tb>>>(W_rec);
    rowsum_k<<<NHID, 256>>>(W_rec);

    dim3 gg(NHID / 128, MROWS / 128);      // (16, 125)
    gemm_k<<<gg, 256>>>(b_in);

    scan_k<<<BATCH, 1024>>>(mem0, b_rec, out);
}